// round 1
// baseline (speedup 1.0000x reference)
#include <cuda_runtime.h>

#define D_MODEL     2048
#define NUM_EXPERTS 64
#define TOP_K       4
#define TM          64   // tokens per block
#define BK          16   // k-chunk

// Deterministic scratch for per-block expert sums (no allocations allowed).
__device__ float g_expert_partial[512 * NUM_EXPERTS];

__global__ __launch_bounds__(256) void router_kernel(
    const float* __restrict__ u, const float* __restrict__ E,
    const float* __restrict__ bias,
    float* __restrict__ out_idx, float* __restrict__ out_val,
    float* __restrict__ out_scores)
{
    __shared__ float uS[TM][BK + 1];            // +1 pad: kill ty bank conflicts
    __shared__ float eS[BK][NUM_EXPERTS];
    __shared__ float L[TM][NUM_EXPERTS + 1];    // logits -> probs

    const int tid = threadIdx.x;
    const int tx = tid & 15;    // expert quad: experts [tx*4, tx*4+4)
    const int ty = tid >> 4;    // token quad:  tokens  [ty*4, ty*4+4)
    const int tokBase = blockIdx.x * TM;

    float acc[4][4];
#pragma unroll
    for (int i = 0; i < 4; i++)
#pragma unroll
        for (int j = 0; j < 4; j++) acc[i][j] = 0.f;

    for (int k0 = 0; k0 < D_MODEL; k0 += BK) {
        // load u tile: 64 rows x 16 cols (1024 floats, 4 per thread, coalesced 64B rows)
#pragma unroll
        for (int i = 0; i < 4; i++) {
            int idx = tid + i * 256;
            int r = idx >> 4, c = idx & 15;
            uS[r][c] = u[(size_t)(tokBase + r) * D_MODEL + k0 + c];
        }
        // load E tile: 16 rows x 64 cols (coalesced 256B rows)
#pragma unroll
        for (int i = 0; i < 4; i++) {
            int idx = tid + i * 256;
            int r = idx >> 6, c = idx & 63;
            eS[r][c] = E[(size_t)(k0 + r) * NUM_EXPERTS + c];
        }
        __syncthreads();

#pragma unroll
        for (int k = 0; k < BK; k++) {
            float a0 = uS[ty * 4 + 0][k];
            float a1 = uS[ty * 4 + 1][k];
            float a2 = uS[ty * 4 + 2][k];
            float a3 = uS[ty * 4 + 3][k];
            float4 b = *reinterpret_cast<const float4*>(&eS[k][tx * 4]);
            acc[0][0] += a0 * b.x; acc[0][1] += a0 * b.y; acc[0][2] += a0 * b.z; acc[0][3] += a0 * b.w;
            acc[1][0] += a1 * b.x; acc[1][1] += a1 * b.y; acc[1][2] += a1 * b.z; acc[1][3] += a1 * b.w;
            acc[2][0] += a2 * b.x; acc[2][1] += a2 * b.y; acc[2][2] += a2 * b.z; acc[2][3] += a2 * b.w;
            acc[3][0] += a3 * b.x; acc[3][1] += a3 * b.y; acc[3][2] += a3 * b.z; acc[3][3] += a3 * b.w;
        }
        __syncthreads();
    }

    // logits (+bias) -> shared
#pragma unroll
    for (int i = 0; i < 4; i++)
#pragma unroll
        for (int j = 0; j < 4; j++)
            L[ty * 4 + i][tx * 4 + j] = acc[i][j] + bias[tx * 4 + j];
    __syncthreads();

    // per-token softmax + top-4: one thread per token (threads 0..63)
    if (tid < TM) {
        const int t = tid;
        float mx = -1e30f;
#pragma unroll 8
        for (int e = 0; e < NUM_EXPERTS; e++) mx = fmaxf(mx, L[t][e]);
        float s = 0.f;
#pragma unroll 8
        for (int e = 0; e < NUM_EXPERTS; e++) {
            float p = expf(L[t][e] - mx);
            L[t][e] = p;
            s += p;
        }
        const float inv = 1.f / s;
#pragma unroll 8
        for (int e = 0; e < NUM_EXPERTS; e++) L[t][e] *= inv;

        unsigned long long chosen = 0ull;
        const int gtok = tokBase + t;
#pragma unroll
        for (int r = 0; r < TOP_K; r++) {
            float bv = -1.f;
            int bi = 0;
            for (int e = 0; e < NUM_EXPERTS; e++) {
                if ((chosen >> e) & 1ull) continue;
                float v = L[t][e];
                if (v > bv) { bv = v; bi = e; }  // strict > : lowest index wins ties
            }
            chosen |= (1ull << bi);
            out_idx[(size_t)gtok * TOP_K + r] = (float)bi;
            out_val[(size_t)gtok * TOP_K + r] = bv;
        }
    }
    __syncthreads();

    // coalesced scores writeback
    for (int idx = tid; idx < TM * NUM_EXPERTS; idx += 256) {
        int t = idx >> 6, e = idx & 63;
        out_scores[(size_t)(tokBase + t) * NUM_EXPERTS + e] = L[t][e];
    }

    // deterministic per-block expert sums
    if (tid < NUM_EXPERTS) {
        int e = tid;
        float s = 0.f;
#pragma unroll 8
        for (int t = 0; t < TM; t++) s += L[t][e];
        g_expert_partial[(size_t)blockIdx.x * NUM_EXPERTS + e] = s;
    }
}

__global__ void aux_kernel(float* __restrict__ out_aux, int nBlocks, int nTok)
{
    __shared__ float red[NUM_EXPERTS];
    const int e = threadIdx.x;   // 64 threads
    float s = 0.f;
    for (int b = 0; b < nBlocks; b++)
        s += g_expert_partial[(size_t)b * NUM_EXPERTS + e];
    float m = s / (float)nTok;
    red[e] = m * m;
    __syncthreads();
    for (int off = 32; off > 0; off >>= 1) {
        if (e < off) red[e] += red[e + off];
        __syncthreads();
    }
    if (e == 0) out_aux[0] = red[0] * (float)NUM_EXPERTS;
}

extern "C" void kernel_launch(void* const* d_in, const int* in_sizes, int n_in,
                              void* d_out, int out_size)
{
    const float* u    = (const float*)d_in[0];
    const float* E    = (const float*)d_in[1];
    const float* bias = (const float*)d_in[2];

    const int nTok = in_sizes[0] / D_MODEL;          // 16384
    float* out        = (float*)d_out;
    float* out_idx    = out;                                         // [nTok, 4]
    float* out_val    = out_idx + (size_t)nTok * TOP_K;              // [nTok, 4]
    float* out_scores = out_val + (size_t)nTok * TOP_K;              // [nTok, 64]
    float* out_aux    = out_scores + (size_t)nTok * NUM_EXPERTS;     // [1]

    const int nBlocks = nTok / TM;                   // 256
    router_kernel<<<nBlocks, 256>>>(u, E, bias, out_idx, out_val, out_scores);
    aux_kernel<<<1, NUM_EXPERTS>>>(out_aux, nBlocks, nTok);
}